// round 6
// baseline (speedup 1.0000x reference)
#include <cuda_runtime.h>

#define B 64
#define CIN 512
#define HIDE 128
#define OP 512
#define HW 4096   // 64*64
#define BPB 4     // batches per head block
#define NBLK (B / BPB)  // 16

// scratch for pooled y [B, CIN]
__device__ float g_y[B * CIN];

__device__ __forceinline__ void prefetch_l2(const void* p) {
    asm volatile("prefetch.global.L2 [%0];" :: "l"(p));
}

// ---------------------------------------------------------------------------
// Kernel 1: global average pool. One block per (b, c) row of 4096 floats.
// (proven config: 87.6% DRAM)
// ---------------------------------------------------------------------------
__global__ __launch_bounds__(256) void pool_kernel(const float* __restrict__ x,
                                                   float* __restrict__ y) {
    cudaTriggerProgrammaticLaunchCompletion();

    const int row = blockIdx.x;
    const float4* p = reinterpret_cast<const float4*>(x + (size_t)row * HW);
    const int t = threadIdx.x;

    float s = 0.0f;
#pragma unroll
    for (int i = 0; i < 4; i++) {
        float4 v = __ldcs(&p[t + i * 256]);
        s += (v.x + v.y) + (v.z + v.w);
    }
#pragma unroll
    for (int o = 16; o > 0; o >>= 1) s += __shfl_xor_sync(0xFFFFFFFFu, s, o);

    __shared__ float sm[8];
    if ((t & 31) == 0) sm[t >> 5] = s;
    __syncthreads();
    if (t < 8) {
        float v = sm[t];
#pragma unroll
        for (int o = 4; o > 0; o >>= 1) v += __shfl_xor_sync(0x000000FFu, v, o);
        if (t == 0) y[row] = v * (1.0f / (float)HW);
    }
}

// ---------------------------------------------------------------------------
// Kernel 2: fused AGCA head, batch-blocked: 16 blocks x 1024 threads,
// each block serves 4 batches so every weight load is reused 4x.
// ---------------------------------------------------------------------------
__global__ __launch_bounds__(1024) void head_kernel(const float* __restrict__ y,
                                                    const float* __restrict__ W1,
                                                    const float* __restrict__ A2,
                                                    const float* __restrict__ w2p,
                                                    const float* __restrict__ w3p,
                                                    const float* __restrict__ W4,
                                                    float* __restrict__ out) {
    const int blk  = blockIdx.x;          // 0..15
    const int b0   = blk * BPB;
    const int tid  = threadIdx.x;
    const int wid  = tid >> 5;            // 0..31
    const int lane = tid & 31;

    // ---- L2 prefetch of this block's 1/16 slice of the weights ----
    {
        const char* w1c = (const char*)W1;   // 256KB = 2048 lines -> 128/blk
        const char* w4c = (const char*)W4;   // 256KB = 2048 lines -> 128/blk
        const char* a2c = (const char*)A2;   //  64KB =  512 lines ->  32/blk
        if (tid < 128) {
            prefetch_l2(w1c + ((size_t)blk * 128 + tid) * 128);
        } else if (tid < 256) {
            prefetch_l2(w4c + ((size_t)blk * 128 + (tid - 128)) * 128);
        } else if (tid < 288) {
            prefetch_l2(a2c + ((size_t)blk * 32 + (tid - 256)) * 128);
        }
    }

    cudaGridDependencySynchronize();

    __shared__ float ys[BPB][CIN];
    __shared__ float y1s[BPB][HIDE];
    __shared__ float a1s[BPB][HIDE];
    __shared__ float y3s[BPB][HIDE];
    __shared__ float redm[BPB][4];
    __shared__ float reds[BPB][4];

    // ---- load pooled rows (coalesced) ----
    for (int i = tid; i < BPB * CIN; i += 1024)
        ys[i >> 9][i & (CIN - 1)] = y[(b0 + (i >> 9)) * CIN + (i & (CIN - 1))];
    __syncthreads();

    // ---- GEMV1: warp wid -> h = wid*4 + {0..3}, 4 batches per load ----
    {
        const int h0 = wid << 2;
        float acc[4][4];
#pragma unroll
        for (int i = 0; i < 4; i++)
#pragma unroll
            for (int bb = 0; bb < 4; bb++) acc[i][bb] = 0.0f;

#pragma unroll
        for (int k = 0; k < CIN / 32; k++) {
            const int c = lane + (k << 5);
            float w[4], yv[4];
#pragma unroll
            for (int i = 0; i < 4; i++) w[i] = __ldg(&W1[(size_t)(h0 + i) * CIN + c]);
#pragma unroll
            for (int bb = 0; bb < 4; bb++) yv[bb] = ys[bb][c];
#pragma unroll
            for (int i = 0; i < 4; i++)
#pragma unroll
                for (int bb = 0; bb < 4; bb++) acc[i][bb] += w[i] * yv[bb];
        }
#pragma unroll
        for (int o = 16; o > 0; o >>= 1)
#pragma unroll
            for (int i = 0; i < 4; i++)
#pragma unroll
                for (int bb = 0; bb < 4; bb++)
                    acc[i][bb] += __shfl_xor_sync(0xFFFFFFFFu, acc[i][bb], o);
        if (lane == 0)
#pragma unroll
            for (int i = 0; i < 4; i++)
#pragma unroll
                for (int bb = 0; bb < 4; bb++) y1s[bb][h0 + i] = acc[i][bb];
    }
    __syncthreads();

    // ---- softmax per batch: threads 0..511 are (b = tid>>7, h = tid&127) ----
    const float w2 = __ldg(w2p);
    if (tid < BPB * HIDE) {
        const int bb = tid >> 7;
        const int h  = tid & (HIDE - 1);
        const float z = w2 * y1s[bb][h];
        float m = z;
#pragma unroll
        for (int o = 16; o > 0; o >>= 1) m = fmaxf(m, __shfl_xor_sync(0xFFFFFFFFu, m, o));
        if (lane == 0) redm[bb][wid & 3] = m;
    }
    __syncthreads();
    if (tid < BPB * HIDE) {
        const int bb = tid >> 7;
        const int h  = tid & (HIDE - 1);
        const float m = fmaxf(fmaxf(redm[bb][0], redm[bb][1]),
                              fmaxf(redm[bb][2], redm[bb][3]));
        const float e = expf(w2 * y1s[bb][h] - m);
        a1s[bb][h] = e;
        float ssum = e;
#pragma unroll
        for (int o = 16; o > 0; o >>= 1) ssum += __shfl_xor_sync(0xFFFFFFFFu, ssum, o);
        if (lane == 0) reds[bb][wid & 3] = ssum;
    }
    __syncthreads();

    // ---- y2/y3: threads 0..511 as (b, h); A2 loads shared across batches ----
    if (tid < BPB * HIDE) {
        const int bb = tid >> 7;
        const int h  = tid & (HIDE - 1);
        const float ssum = (reds[bb][0] + reds[bb][1]) + (reds[bb][2] + reds[bb][3]);
        const float a1n = a1s[bb][h] / ssum;
        float t = y1s[bb][h] * a1n;
#pragma unroll 16
        for (int j = 0; j < HIDE; j++) t += y1s[bb][j] * __ldg(&A2[j * HIDE + h]);
        const float w3 = __ldg(w3p);
        y3s[bb][h] = fmaxf(w3 * t, 0.0f);
    }
    __syncthreads();

    // ---- GEMV4: warp wid owns 16 outputs x 4 batches, 4 passes of 4x4 ----
#pragma unroll
    for (int pass = 0; pass < 4; pass++) {
        const int o0 = (wid << 4) + (pass << 2);
        float acc[4][4];
#pragma unroll
        for (int i = 0; i < 4; i++)
#pragma unroll
            for (int bb = 0; bb < 4; bb++) acc[i][bb] = 0.0f;

#pragma unroll
        for (int k = 0; k < HIDE / 32; k++) {
            const int j = lane + (k << 5);
            float w[4], yv[4];
#pragma unroll
            for (int i = 0; i < 4; i++) w[i] = __ldg(&W4[(size_t)(o0 + i) * HIDE + j]);
#pragma unroll
            for (int bb = 0; bb < 4; bb++) yv[bb] = y3s[bb][j];
#pragma unroll
            for (int i = 0; i < 4; i++)
#pragma unroll
                for (int bb = 0; bb < 4; bb++) acc[i][bb] += w[i] * yv[bb];
        }
#pragma unroll
        for (int off = 16; off > 0; off >>= 1)
#pragma unroll
            for (int i = 0; i < 4; i++)
#pragma unroll
                for (int bb = 0; bb < 4; bb++)
                    acc[i][bb] += __shfl_xor_sync(0xFFFFFFFFu, acc[i][bb], off);

        if (lane == 0) {
#pragma unroll
            for (int i = 0; i < 4; i++)
#pragma unroll
                for (int bb = 0; bb < 4; bb++)
                    out[(b0 + bb) * OP + o0 + i] = 1.0f / (1.0f + expf(-acc[i][bb]));
        }
    }
}

extern "C" void kernel_launch(void* const* d_in, const int* in_sizes, int n_in,
                              void* d_out, int out_size) {
    const float* x  = (const float*)d_in[0];
    const float* W1 = (const float*)d_in[1];
    const float* A2 = (const float*)d_in[2];
    const float* w2 = (const float*)d_in[3];
    const float* w3 = (const float*)d_in[4];
    const float* W4 = (const float*)d_in[5];
    float* out = (float*)d_out;

    float* yscratch;
    cudaGetSymbolAddress((void**)&yscratch, g_y);

    pool_kernel<<<B * CIN, 256>>>(x, yscratch);

    cudaLaunchConfig_t cfg = {};
    cfg.gridDim = dim3(NBLK);
    cfg.blockDim = dim3(1024);
    cfg.dynamicSmemBytes = 0;
    cfg.stream = 0;
    cudaLaunchAttribute attr[1];
    attr[0].id = cudaLaunchAttributeProgrammaticStreamSerialization;
    attr[0].val.programmaticStreamSerializationAllowed = 1;
    cfg.attrs = attr;
    cfg.numAttrs = 1;
    cudaLaunchKernelEx(&cfg, head_kernel, (const float*)yscratch, W1, A2, w2, w3, W4, out);
}